// round 3
// baseline (speedup 1.0000x reference)
#include <cuda_runtime.h>
#include <math.h>

#define NDAG  16384
#define NNODE 48
#define D     62
#define DP    64
#define NCLS  500
#define DPC   2     // dags per CTA in scan kernel

// -------- scratch (static device globals; no runtime allocation) ----------
__device__ float g_atomP[(size_t)NDAG * NNODE * D];  // W_merge[:,62:]@atom + b_merge
__device__ float g_last[(size_t)NDAG * D];           // sink outputs per DAG
__device__ float g_logit[NDAG];                      // last . dag_w
__device__ float g_partmax[64];                      // per-block logit max
__device__ float g_part[64 * 64];                    // [c][0..61]=pool numerator, [62]=sumE

// ============================================================================
// K1: atomP[d,t,g] = b_merge[g] + sum_k W_merge[g][62+k] * atoms[d,t,k]
// One thread per node. Atom row in registers, W broadcast from shared.
// ============================================================================
__global__ void __launch_bounds__(128) k_atomP(const float* __restrict__ atoms,
                                               const float* __restrict__ W_merge,
                                               const float* __restrict__ b_merge) {
    __shared__ float Ws[D][DP];   // Ws[g][k] = W_merge[g][62+k], zero-padded
    __shared__ float bs[DP];
    int tid = threadIdx.x;
    for (int i = tid; i < D * DP; i += 128) {
        int g = i >> 6, k = i & 63;
        Ws[g][k] = (k < D) ? W_merge[g * (2 * D) + D + k] : 0.f;
    }
    if (tid < DP) bs[tid] = (tid < D) ? b_merge[tid] : 0.f;
    __syncthreads();

    long node = (long)blockIdx.x * 128 + tid;            // exact multiple
    const float* arow = atoms + node * D;
    float a[DP];
#pragma unroll
    for (int k = 0; k < 31; k++) {                        // rows are 8B aligned
        float2 v = *(const float2*)(arow + 2 * k);
        a[2 * k] = v.x; a[2 * k + 1] = v.y;
    }
    a[62] = 0.f; a[63] = 0.f;

    float* orow = g_atomP + node * D;
#pragma unroll 2
    for (int gg = 0; gg < D; gg++) {
        float acc = bs[gg];
#pragma unroll
        for (int k = 0; k < DP; k += 4) {
            float4 w = *(const float4*)&Ws[gg][k];        // warp-uniform -> broadcast
            acc += a[k] * w.x + a[k + 1] * w.y + a[k + 2] * w.z + a[k + 3] * w.w;
        }
        orow[gg] = acc;
    }
}

// ============================================================================
// K2: sequential DAG scan. 2 DAGs per CTA, 64 threads per DAG (thread = out dim).
// Stores z[t] = W_agg @ out[t] and sdot[t] = out[t].att_w instead of raw outs:
//   merged = relu( (sum_p a_p z[p]) + atomP[t] )
// ============================================================================
__global__ void __launch_bounds__(128) k_scan(const float* __restrict__ atoms,
                                              const int*   __restrict__ preds,
                                              const float* __restrict__ W_single,
                                              const float* __restrict__ b_single,
                                              const float* __restrict__ W_merge,
                                              const float* __restrict__ att_w) {
    __shared__ float z_sh[DPC][NNODE][DP];
    __shared__ float out_sh[DPC][DP];
    __shared__ float sdot_sh[DPC][NNODE];
    __shared__ float Ws[D][DP];        // TRANSPOSED: Ws[k][g] = W_single[g][k]
    __shared__ float attw[DP], bsg[DP];

    int tid = threadIdx.x;
    int dl  = tid >> 6;                // local dag 0/1 (warp-uniform)
    int g   = tid & 63;                // output dim
    long d  = (long)blockIdx.x * DPC + dl;

    for (int i = tid; i < D * DP; i += 128) {
        int k = i >> 6, c = i & 63;
        Ws[k][c] = (c < D) ? W_single[c * D + k] : 0.f;
    }
    if (tid < DP) {
        attw[tid] = (tid < D) ? att_w[tid] : 0.f;
        bsg[tid]  = (tid < D) ? b_single[tid] : 0.f;
    }
    // W_agg row (first 62 cols of W_merge) in registers
    float Wr[DP];
#pragma unroll
    for (int k = 0; k < D; k++) Wr[k] = (g < D) ? W_merge[g * (2 * D) + k] : 0.f;
    Wr[62] = 0.f; Wr[63] = 0.f;
    __syncthreads();

    for (int t = 0; t < NNODE; t++) {
        int4 pv = *(const int4*)(preds + (d * NNODE + t) * 4);
        float outv;
        bool has = (pv.x >= 0) | (pv.y >= 0) | (pv.z >= 0) | (pv.w >= 0);
        if (has) {
            float s0 = (pv.x >= 0) ? sdot_sh[dl][pv.x] : -3.0e38f;
            float s1 = (pv.y >= 0) ? sdot_sh[dl][pv.y] : -3.0e38f;
            float s2 = (pv.z >= 0) ? sdot_sh[dl][pv.z] : -3.0e38f;
            float s3 = (pv.w >= 0) ? sdot_sh[dl][pv.w] : -3.0e38f;
            float m = fmaxf(fmaxf(s0, s1), fmaxf(s2, s3));
            float e0 = (pv.x >= 0) ? expf(s0 - m) : 0.f;
            float e1 = (pv.y >= 0) ? expf(s1 - m) : 0.f;
            float e2 = (pv.z >= 0) ? expf(s2 - m) : 0.f;
            float e3 = (pv.w >= 0) ? expf(s3 - m) : 0.f;
            float sum = e0 + e1 + e2 + e3;
            int p0 = pv.x < 0 ? 0 : pv.x;
            int p1 = pv.y < 0 ? 0 : pv.y;
            int p2 = pv.z < 0 ? 0 : pv.z;
            int p3 = pv.w < 0 ? 0 : pv.w;
            float za = e0 * z_sh[dl][p0][g] + e1 * z_sh[dl][p1][g]
                     + e2 * z_sh[dl][p2][g] + e3 * z_sh[dl][p3][g];
            float mp = (g < D) ? g_atomP[(d * NNODE + t) * D + g] : 0.f;
            outv = fmaxf(mp + za / sum, 0.f);
        } else {
            // rare path (t=0 always, t>0 with p~0.0016): single = relu(W_single@atom + b)
            const float* arow = atoms + (d * NNODE + t) * D;
            float acc = bsg[g];
#pragma unroll
            for (int k = 0; k < 31; k++) {
                float2 v = *(const float2*)(arow + 2 * k);   // warp-uniform LDG
                acc += Ws[2 * k][g] * v.x + Ws[2 * k + 1][g] * v.y;
            }
            outv = fmaxf(acc, 0.f);
        }
        out_sh[dl][g] = (g < D) ? outv : 0.f;
        __syncthreads();

        if (g < D) {
            float z0 = 0.f, z1 = 0.f, z2 = 0.f, z3 = 0.f;
#pragma unroll
            for (int k = 0; k < DP; k += 4) {
                float4 o = *(const float4*)&out_sh[dl][k];   // broadcast
                z0 += Wr[k]     * o.x;  z1 += Wr[k + 1] * o.y;
                z2 += Wr[k + 2] * o.z;  z3 += Wr[k + 3] * o.w;
            }
            z_sh[dl][t][g] = (z0 + z1) + (z2 + z3);
            if (t == NNODE - 1) g_last[d * D + g] = outv;
        } else if (g == D) {
            float s0 = 0.f, s1 = 0.f, s2 = 0.f, s3 = 0.f;
#pragma unroll
            for (int k = 0; k < DP; k += 4) {
                s0 += out_sh[dl][k]     * attw[k];
                s1 += out_sh[dl][k + 1] * attw[k + 1];
                s2 += out_sh[dl][k + 2] * attw[k + 2];
                s3 += out_sh[dl][k + 3] * attw[k + 3];
            }
            sdot_sh[dl][t] = (s0 + s1) + (s2 + s3);
        }
        __syncthreads();
    }
}

// ============================================================================
// K3: logits l[d] = last[d].dag_w, plus per-block max
// ============================================================================
__global__ void __launch_bounds__(256) k_logit(const float* __restrict__ dag_w) {
    __shared__ float dw[D];
    __shared__ float red[256];
    int tid = threadIdx.x;
    if (tid < D) dw[tid] = dag_w[tid];
    __syncthreads();
    long dd = (long)blockIdx.x * 256 + tid;
    const float* row = g_last + dd * D;
    float l = 0.f;
#pragma unroll
    for (int k = 0; k < D; k++) l += row[k] * dw[k];
    g_logit[dd] = l;
    red[tid] = l;
    __syncthreads();
    for (int s = 128; s > 0; s >>= 1) {
        if (tid < s) red[tid] = fmaxf(red[tid], red[tid + s]);
        __syncthreads();
    }
    if (tid == 0) g_partmax[blockIdx.x] = red[0];
}

// ============================================================================
// K4: per-block partial softmax-pool (recomputes global max from partials)
// ============================================================================
__global__ void __launch_bounds__(64) k_pool() {
    __shared__ float red[64];
    int tid = threadIdx.x;
    red[tid] = g_partmax[tid];
    __syncthreads();
    for (int s = 32; s > 0; s >>= 1) {
        if (tid < s) red[tid] = fmaxf(red[tid], red[tid + s]);
        __syncthreads();
    }
    float M = red[0];
    long base = (long)blockIdx.x * 256;
    float pool = 0.f, sumE = 0.f;
    for (int i = 0; i < 256; i++) {
        long dd = base + i;
        float e = expf(g_logit[dd] - M);
        sumE += e;
        if (tid < D) pool += e * g_last[dd * D + tid];
    }
    if (tid < D)       g_part[blockIdx.x * 64 + tid] = pool;
    else if (tid == D) g_part[blockIdx.x * 64 + D]   = sumE;
}

// ============================================================================
// K5: reduce partials -> pooled; final = sigmoid(W_final @ pooled + b_final)
// ============================================================================
__global__ void __launch_bounds__(512) k_final(const float* __restrict__ W_final,
                                               const float* __restrict__ b_final,
                                               float* __restrict__ out) {
    __shared__ float pooled[D];
    __shared__ float sE;
    int tid = threadIdx.x;
    if (tid <= D) {
        float s = 0.f;
        for (int c = 0; c < 64; c++) s += g_part[c * 64 + tid];
        if (tid < D) pooled[tid] = s;
        else sE = s;
    }
    __syncthreads();
    float inv = 1.f / sE;
    __syncthreads();
    if (tid < D) pooled[tid] *= inv;
    __syncthreads();
    if (tid < NCLS) {
        float acc = b_final[tid];
#pragma unroll
        for (int k = 0; k < D; k++) acc += W_final[tid * D + k] * pooled[k];
        out[tid] = 1.f / (1.f + expf(-acc));
    }
}

// ============================================================================
extern "C" void kernel_launch(void* const* d_in, const int* in_sizes, int n_in,
                              void* d_out, int out_size) {
    const float* atoms    = (const float*)d_in[0];
    const int*   preds    = (const int*)  d_in[1];
    const float* W_single = (const float*)d_in[2];
    const float* b_single = (const float*)d_in[3];
    const float* W_merge  = (const float*)d_in[4];
    const float* b_merge  = (const float*)d_in[5];
    const float* att_w    = (const float*)d_in[6];
    const float* dag_w    = (const float*)d_in[7];
    const float* W_final  = (const float*)d_in[8];
    const float* b_final  = (const float*)d_in[9];
    float* out = (float*)d_out;

    k_atomP<<<NDAG * NNODE / 128, 128>>>(atoms, W_merge, b_merge);
    k_scan<<<NDAG / DPC, 128>>>(atoms, preds, W_single, b_single, W_merge, att_w);
    k_logit<<<NDAG / 256, 256>>>(dag_w);
    k_pool<<<64, 64>>>();
    k_final<<<1, 512>>>(W_final, b_final, out);
}